// round 1
// baseline (speedup 1.0000x reference)
#include <cuda_runtime.h>
#include <cuda_bf16.h>

#define DIMS 128
#define TILE_M 128
#define SROW 132   // smem row stride in floats (16B aligned, bank-spread with row-step-4 access)

__device__ int g_idx_is64;

// ---------------------------------------------------------------------------
// Detect whether edge_index is int64 or int32.
// If the buffer really holds int64 node ids (< n_nodes < 2^31), the high 32
// bits of every 8-byte word are 0. If it holds int32 ids, an int64 read
// combines two random ids -> huge value. 32 probes => false positive ~1e-160.
// ---------------------------------------------------------------------------
__global__ void detect_idx_kernel(const void* eidx, long long n_nodes) {
    const long long* p = (const long long*)eidx;
    int ok = 1;
    for (int i = 0; i < 32; i++) {
        long long v = p[i];
        if (v < 0 || v >= n_nodes) ok = 0;
    }
    g_idx_is64 = ok;
}

// ---------------------------------------------------------------------------
// Tile helpers (256 threads)
// ---------------------------------------------------------------------------
__device__ __forceinline__ void load_tile_gmem(const float* __restrict__ g,
                                               int row0, int nvalid, float* s) {
    int tid = threadIdx.x;
    #pragma unroll 4
    for (int idx = tid; idx < TILE_M * 32; idx += 256) {
        int row = idx >> 5;
        int kc  = idx & 31;
        float4 v = make_float4(0.f, 0.f, 0.f, 0.f);
        if (row < nvalid)
            v = *(const float4*)(g + (size_t)(row0 + row) * DIMS + kc * 4);
        *(float4*)(s + row * SROW + kc * 4) = v;
    }
}

__device__ __forceinline__ void load_w(const float* __restrict__ w, float* s) {
    int tid = threadIdx.x;
    #pragma unroll 4
    for (int idx = tid; idx < DIMS * 32; idx += 256) {
        int row = idx >> 5;
        int kc  = idx & 31;
        *(float4*)(s + row * SROW + kc * 4) =
            *(const float4*)(w + row * DIMS + kc * 4);
    }
}

__device__ __forceinline__ void store_tile(const float* __restrict__ s,
                                           float* __restrict__ g,
                                           int row0, int nvalid) {
    int tid = threadIdx.x;
    #pragma unroll 4
    for (int idx = tid; idx < TILE_M * 32; idx += 256) {
        int row = idx >> 5;
        int kc  = idx & 31;
        if (row < nvalid)
            *(float4*)(g + (size_t)(row0 + row) * DIMS + kc * 4) =
                *(const float4*)(s + row * SROW + kc * 4);
    }
}

// ---------------------------------------------------------------------------
// 128x128x128 GEMM microkernel: out[r][c] = sum_k A[r][k]*B[c][k]
// 8 warps as 4(row) x 2(col). Warp tile 32x64. Lane: lr=lane>>3, lc=lane&7.
// Thread rows: wr*32 + lr + 4*i  (i=0..7)  -> A-load banks {4*lr}+k, bcast x8
// Thread cols: wc*64 + lc + 8*j  (j=0..7)  -> B-load banks {4*lc}+k, full spread
// ---------------------------------------------------------------------------
__device__ __forceinline__ void gemm_tile(const float* __restrict__ As,
                                          const float* __restrict__ Bs,
                                          float acc[8][8]) {
    int wid  = threadIdx.x >> 5;
    int lane = threadIdx.x & 31;
    int wr = wid & 3, wc = wid >> 2;
    int lr = lane >> 3, lc = lane & 7;
    const float* Ab = As + (wr * 32 + lr) * SROW;
    const float* Bb = Bs + (wc * 64 + lc) * SROW;

    #pragma unroll 2
    for (int k = 0; k < DIMS; k += 4) {
        float4 a[8], b[8];
        #pragma unroll
        for (int i = 0; i < 8; i++) a[i] = *(const float4*)(Ab + (4 * i) * SROW + k);
        #pragma unroll
        for (int j = 0; j < 8; j++) b[j] = *(const float4*)(Bb + (8 * j) * SROW + k);
        #pragma unroll
        for (int i = 0; i < 8; i++) {
            #pragma unroll
            for (int j = 0; j < 8; j++) {
                acc[i][j] = fmaf(a[i].x, b[j].x, acc[i][j]);
                acc[i][j] = fmaf(a[i].y, b[j].y, acc[i][j]);
                acc[i][j] = fmaf(a[i].z, b[j].z, acc[i][j]);
                acc[i][j] = fmaf(a[i].w, b[j].w, acc[i][j]);
            }
        }
    }
}

__device__ __forceinline__ void acc_zero(float acc[8][8]) {
    #pragma unroll
    for (int i = 0; i < 8; i++)
        #pragma unroll
        for (int j = 0; j < 8; j++) acc[i][j] = 0.f;
}

__device__ __forceinline__ void acc_to_smem(const float acc[8][8], float* Cs) {
    int wid  = threadIdx.x >> 5;
    int lane = threadIdx.x & 31;
    int wr = wid & 3, wc = wid >> 2;
    int lr = lane >> 3, lc = lane & 7;
    #pragma unroll
    for (int i = 0; i < 8; i++) {
        int r = wr * 32 + lr + 4 * i;
        #pragma unroll
        for (int j = 0; j < 8; j++) {
            int c = wc * 64 + lc + 8 * j;
            Cs[r * SROW + c] = acc[i][j];
        }
    }
}

// ---------------------------------------------------------------------------
// Node kernel: src_embed = x @ W_src^T ; rx_embed = x @ W_rx^T
// smem: As (x tile) | B1 (W_src, later reused as output stage) | B2 (W_rx)
// ---------------------------------------------------------------------------
extern __shared__ float smem[];

__global__ void __launch_bounds__(256, 1)
node_kernel(const float* __restrict__ x,
            const float* __restrict__ Wsrc,
            const float* __restrict__ Wrx,
            float* __restrict__ out_src,
            float* __restrict__ out_rx,
            int n_nodes) {
    float* As = smem;
    float* B1 = smem + TILE_M * SROW;
    float* B2 = B1 + DIMS * SROW;

    int row0   = blockIdx.x * TILE_M;
    int nvalid = min(TILE_M, n_nodes - row0);

    load_tile_gmem(x, row0, nvalid, As);
    load_w(Wsrc, B1);
    load_w(Wrx, B2);
    __syncthreads();

    float acc[8][8];
    acc_zero(acc);
    gemm_tile(As, B1, acc);
    __syncthreads();            // everyone done reading W_src
    acc_to_smem(acc, B1);       // stage src_embed into B1
    __syncthreads();
    store_tile(B1, out_src, row0, nvalid);

    acc_zero(acc);
    gemm_tile(As, B2, acc);
    __syncthreads();            // store_tile (above) + gemm reads done
    acc_to_smem(acc, B1);       // stage rx_embed
    __syncthreads();
    store_tile(B1, out_rx, row0, nvalid);
}

// ---------------------------------------------------------------------------
// Edge kernel: edge_embed = edge_attr @ W_edge^T (written out);
//   agg = edge_embed + src_embed[u] + rx_embed[v] (in smem);
//   updated = agg @ W_agg^T (written out).
// smem: As (edge_attr tile, reused for edge_embed/agg) | B1 (W_edge / stage) | B2 (W_agg)
// ---------------------------------------------------------------------------
__global__ void __launch_bounds__(256, 1)
edge_kernel(const float* __restrict__ eattr,
            const void*  __restrict__ eidx,
            const float* __restrict__ Wedge,
            const float* __restrict__ Wagg,
            const float* __restrict__ src_embed,
            const float* __restrict__ rx_embed,
            float* __restrict__ out_edge,
            float* __restrict__ out_upd,
            int n_edges) {
    float* As = smem;
    float* B1 = smem + TILE_M * SROW;
    float* B2 = B1 + DIMS * SROW;

    int row0   = blockIdx.x * TILE_M;
    int nvalid = min(TILE_M, n_edges - row0);

    load_tile_gmem(eattr, row0, nvalid, As);
    load_w(Wedge, B1);
    load_w(Wagg, B2);
    __syncthreads();

    float acc[8][8];
    acc_zero(acc);
    gemm_tile(As, B1, acc);     // edge_embed
    __syncthreads();            // all reads of As (edge_attr) done
    acc_to_smem(acc, As);       // edge_embed now in As
    __syncthreads();

    // Fused: write edge_embed out + gather-add src[u] + rx[v] into As.
    {
        int is64 = g_idx_is64;
        const int*       pi32 = (const int*)eidx;
        const long long* pi64 = (const long long*)eidx;
        int tid = threadIdx.x;
        #pragma unroll 4
        for (int idx = tid; idx < TILE_M * 32; idx += 256) {
            int row = idx >> 5;
            int kc  = idx & 31;
            if (row < nvalid) {
                size_t e = (size_t)(row0 + row);
                long long u, v;
                if (is64) { u = pi64[e]; v = pi64[(size_t)n_edges + e]; }
                else      { u = pi32[e]; v = pi32[(size_t)n_edges + e]; }
                float4 a = *(float4*)(As + row * SROW + kc * 4);
                *(float4*)(out_edge + e * DIMS + kc * 4) = a;
                float4 su = *(const float4*)(src_embed + (size_t)u * DIMS + kc * 4);
                float4 rv = *(const float4*)(rx_embed  + (size_t)v * DIMS + kc * 4);
                a.x += su.x + rv.x;
                a.y += su.y + rv.y;
                a.z += su.z + rv.z;
                a.w += su.w + rv.w;
                *(float4*)(As + row * SROW + kc * 4) = a;
            }
        }
    }
    __syncthreads();

    acc_zero(acc);
    gemm_tile(As, B2, acc);     // updated_edge
    __syncthreads();            // all reads of W_edge staging buffer done
    acc_to_smem(acc, B1);
    __syncthreads();
    store_tile(B1, out_upd, row0, nvalid);
}

// ---------------------------------------------------------------------------
// Launch
// Inputs: x, edge_index, edge_attr, W_src, W_edge, W_rx, W_agg
// Output: concat(src_embed[N,D], edge_embed[E,D], rx_embed[N,D], updated[E,D])
// ---------------------------------------------------------------------------
extern "C" void kernel_launch(void* const* d_in, const int* in_sizes, int n_in,
                              void* d_out, int out_size) {
    const float* x     = (const float*)d_in[0];
    const void*  eidx  = d_in[1];
    const float* eattr = (const float*)d_in[2];
    const float* Wsrc  = (const float*)d_in[3];
    const float* Wedge = (const float*)d_in[4];
    const float* Wrx   = (const float*)d_in[5];
    const float* Wagg  = (const float*)d_in[6];

    int N = in_sizes[0] / DIMS;
    int E = in_sizes[2] / DIMS;

    float* out      = (float*)d_out;
    float* out_src  = out;
    float* out_edge = out_src + (size_t)N * DIMS;
    float* out_rx   = out_edge + (size_t)E * DIMS;
    float* out_upd  = out_rx + (size_t)N * DIMS;

    size_t smem_bytes = (size_t)(TILE_M + 2 * DIMS) * SROW * sizeof(float); // ~203 KB
    cudaFuncSetAttribute(node_kernel, cudaFuncAttributeMaxDynamicSharedMemorySize,
                         (int)smem_bytes);
    cudaFuncSetAttribute(edge_kernel, cudaFuncAttributeMaxDynamicSharedMemorySize,
                         (int)smem_bytes);

    detect_idx_kernel<<<1, 1>>>(eidx, (long long)N);
    node_kernel<<<(N + TILE_M - 1) / TILE_M, 256, smem_bytes>>>(
        x, Wsrc, Wrx, out_src, out_rx, N);
    edge_kernel<<<(E + TILE_M - 1) / TILE_M, 256, smem_bytes>>>(
        eattr, eidx, Wedge, Wagg, out_src, out_rx, out_edge, out_upd, E);
}

// round 4
// speedup vs baseline: 2.2163x; 2.2163x over previous
#include <cuda_runtime.h>
#include <cstdint>

#define DIMS 128
#define TILE_M 128
#define SROW 132   // smem row stride in floats; (4*row + col) % 32 spreads banks

__device__ int g_idx_is64;

// ---------------------------------------------------------------------------
// edge_index dtype detection (int64 vs int32). int64 ids < N have zero high
// words; int32 pairs read as int64 are astronomically out of range.
// ---------------------------------------------------------------------------
__global__ void detect_idx_kernel(const void* eidx, long long n_nodes) {
    const long long* p = (const long long*)eidx;
    int ok = 1;
    for (int i = 0; i < 32; i++) {
        long long v = p[i];
        if (v < 0 || v >= n_nodes) ok = 0;
    }
    g_idx_is64 = ok;
}

// ---------------------------------------------------------------------------
// Helpers
// ---------------------------------------------------------------------------
__device__ __forceinline__ float f2tf_rna(float f) {
    uint32_t o;
    asm("cvt.rna.tf32.f32 %0, %1;" : "=r"(o) : "f"(f));
    return __uint_as_float(o);
}

__device__ __forceinline__ void mma8(float c[4], const uint32_t a[4],
                                     const uint32_t b[2]) {
    asm volatile(
        "mma.sync.aligned.m16n8k8.row.col.f32.tf32.tf32.f32 "
        "{%0,%1,%2,%3}, {%4,%5,%6,%7}, {%8,%9}, {%0,%1,%2,%3};"
        : "+f"(c[0]), "+f"(c[1]), "+f"(c[2]), "+f"(c[3])
        : "r"(a[0]), "r"(a[1]), "r"(a[2]), "r"(a[3]), "r"(b[0]), "r"(b[1]));
}

// Load gmem tile [*,128] fp32 -> smem, rounding to tf32 (RNA).
__device__ __forceinline__ void load_tile(const float* __restrict__ g, int row0,
                                          int nvalid, float* s) {
    int tid = threadIdx.x;
    #pragma unroll 4
    for (int idx = tid; idx < TILE_M * 32; idx += 256) {
        int row = idx >> 5;
        int kc  = idx & 31;
        float4 v = make_float4(0.f, 0.f, 0.f, 0.f);
        if (row < nvalid)
            v = *(const float4*)(g + (size_t)(row0 + row) * DIMS + kc * 4);
        v.x = f2tf_rna(v.x); v.y = f2tf_rna(v.y);
        v.z = f2tf_rna(v.z); v.w = f2tf_rna(v.w);
        *(float4*)(s + row * SROW + kc * 4) = v;
    }
}

__device__ __forceinline__ void load_w(const float* __restrict__ w, float* s) {
    int tid = threadIdx.x;
    #pragma unroll 4
    for (int idx = tid; idx < DIMS * 32; idx += 256) {
        int row = idx >> 5;
        int kc  = idx & 31;
        float4 v = *(const float4*)(w + row * DIMS + kc * 4);
        v.x = f2tf_rna(v.x); v.y = f2tf_rna(v.y);
        v.z = f2tf_rna(v.z); v.w = f2tf_rna(v.w);
        *(float4*)(s + row * SROW + kc * 4) = v;
    }
}

// ---------------------------------------------------------------------------
// 128x128x128 warp-tiled tf32 mma microkernel.
// 8 warps: wr=wid&3 (row), wc=wid>>2 (col). Warp tile 32(M) x 64(N).
// Per warp: 2 m-tiles (m16) x 8 n-tiles (n8) x 16 k-steps (k8).
// Accum c[i][j][4]; mapping (qr=lane>>2, qc=lane&3):
//   row = wr*32 + i*16 + qr + 8*h   (h=0 -> regs 0,1; h=1 -> regs 2,3)
//   col = wc*64 + j*8 + qc*2 (+1)
// ---------------------------------------------------------------------------
__device__ __forceinline__ void gemm_tile(const float* __restrict__ As,
                                          const float* __restrict__ Bs,
                                          float c[2][8][4]) {
    int wid  = threadIdx.x >> 5, lane = threadIdx.x & 31;
    int wr = wid & 3, wc = wid >> 2;
    int qr = lane >> 2, qc = lane & 3;
    const float* Ab = As + (wr * 32 + qr) * SROW + qc;
    const float* Bb = Bs + (wc * 64 + qr) * SROW + qc;

    #pragma unroll 4
    for (int k = 0; k < DIMS; k += 8) {
        uint32_t a[2][4], b[8][2];
        #pragma unroll
        for (int i = 0; i < 2; i++) {
            const float* p = Ab + i * 16 * SROW + k;
            a[i][0] = __float_as_uint(p[0]);
            a[i][1] = __float_as_uint(p[8 * SROW]);
            a[i][2] = __float_as_uint(p[4]);
            a[i][3] = __float_as_uint(p[8 * SROW + 4]);
        }
        #pragma unroll
        for (int j = 0; j < 8; j++) {
            const float* p = Bb + j * 8 * SROW + k;
            b[j][0] = __float_as_uint(p[0]);
            b[j][1] = __float_as_uint(p[4]);
        }
        #pragma unroll
        for (int i = 0; i < 2; i++)
            #pragma unroll
            for (int j = 0; j < 8; j++) mma8(c[i][j], a[i], b[j]);
    }
}

__device__ __forceinline__ void acc_zero(float c[2][8][4]) {
    #pragma unroll
    for (int i = 0; i < 2; i++)
        #pragma unroll
        for (int j = 0; j < 8; j++)
            #pragma unroll
            for (int q = 0; q < 4; q++) c[i][j][q] = 0.f;
}

// ---------------------------------------------------------------------------
// Node kernel: src_embed = x @ W_src^T ; rx_embed = x @ W_rx^T
// ---------------------------------------------------------------------------
extern __shared__ float smem[];

__global__ void __launch_bounds__(256, 1)
node_kernel(const float* __restrict__ x, const float* __restrict__ Wsrc,
            const float* __restrict__ Wrx, float* __restrict__ out_src,
            float* __restrict__ out_rx, int n_nodes) {
    float* As = smem;
    float* B1 = smem + TILE_M * SROW;
    float* B2 = B1 + DIMS * SROW;

    int row0   = blockIdx.x * TILE_M;
    int nvalid = min(TILE_M, n_nodes - row0);

    load_tile(x, row0, nvalid, As);
    load_w(Wsrc, B1);
    load_w(Wrx, B2);
    __syncthreads();

    int wid = threadIdx.x >> 5, lane = threadIdx.x & 31;
    int wr = wid & 3, wc = wid >> 2;
    int qr = lane >> 2, qc = lane & 3;

    float c[2][8][4];

    #pragma unroll
    for (int g = 0; g < 2; g++) {
        float* outp = g ? out_rx : out_src;
        acc_zero(c);
        gemm_tile(As, g ? B2 : B1, c);
        #pragma unroll
        for (int i = 0; i < 2; i++) {
            #pragma unroll
            for (int h = 0; h < 2; h++) {
                int r = wr * 32 + i * 16 + qr + 8 * h;
                if (r < nvalid) {
                    float* gp = outp + (size_t)(row0 + r) * DIMS + wc * 64 + qc * 2;
                    #pragma unroll
                    for (int j = 0; j < 8; j++)
                        *(float2*)(gp + j * 8) =
                            make_float2(c[i][j][2 * h], c[i][j][2 * h + 1]);
                }
            }
        }
    }
}

// ---------------------------------------------------------------------------
// Edge kernel: edge_embed = edge_attr @ W_edge^T (written out);
//   agg = edge_embed + src_embed[u] + rx_embed[v]  (rebuilt into A tile, tf32);
//   updated = agg @ W_agg^T (written out).
// ---------------------------------------------------------------------------
__global__ void __launch_bounds__(256, 1)
edge_kernel(const float* __restrict__ eattr, const void* __restrict__ eidx,
            const float* __restrict__ Wedge, const float* __restrict__ Wagg,
            const float* __restrict__ src_embed, const float* __restrict__ rx_embed,
            float* __restrict__ out_edge, float* __restrict__ out_upd, int n_edges) {
    float* As = smem;
    float* B1 = smem + TILE_M * SROW;
    float* B2 = B1 + DIMS * SROW;

    int row0   = blockIdx.x * TILE_M;
    int nvalid = min(TILE_M, n_edges - row0);

    load_tile(eattr, row0, nvalid, As);
    load_w(Wedge, B1);
    load_w(Wagg, B2);
    __syncthreads();

    int wid = threadIdx.x >> 5, lane = threadIdx.x & 31;
    int wr = wid & 3, wc = wid >> 2;
    int qr = lane >> 2, qc = lane & 3;

    float c[2][8][4];
    acc_zero(c);
    gemm_tile(As, B1, c);        // edge_embed in regs
    __syncthreads();             // everyone done reading As (edge_attr)

    // Epilogue 1: write edge_embed, gather src[u]+rx[v], store tf32(agg) to As.
    {
        int is64 = g_idx_is64;
        const long long* p64 = (const long long*)eidx;
        const int*       p32 = (const int*)eidx;
        #pragma unroll
        for (int i = 0; i < 2; i++) {
            #pragma unroll
            for (int h = 0; h < 2; h++) {
                int r = wr * 32 + i * 16 + qr + 8 * h;
                if (r < nvalid) {
                    size_t e = (size_t)(row0 + r);
                    long long u, v;
                    if (is64) { u = p64[e]; v = p64[(size_t)n_edges + e]; }
                    else      { u = p32[e]; v = p32[(size_t)n_edges + e]; }
                    int colb = wc * 64 + qc * 2;
                    float* ge = out_edge + e * DIMS + colb;
                    const float* su = src_embed + (size_t)u * DIMS + colb;
                    const float* rv = rx_embed  + (size_t)v * DIMS + colb;
                    float* sa = As + r * SROW + colb;
                    #pragma unroll
                    for (int j = 0; j < 8; j++) {
                        float2 a = make_float2(c[i][j][2 * h], c[i][j][2 * h + 1]);
                        *(float2*)(ge + j * 8) = a;          // edge_embed out
                        float2 s2 = *(const float2*)(su + j * 8);
                        float2 r2 = *(const float2*)(rv + j * 8);
                        a.x = f2tf_rna(a.x + s2.x + r2.x);
                        a.y = f2tf_rna(a.y + s2.y + r2.y);
                        *(float2*)(sa + j * 8) = a;          // agg (tf32) to smem
                    }
                }
            }
        }
    }
    __syncthreads();

    // GEMM2: updated_edge = agg @ W_agg^T
    acc_zero(c);
    gemm_tile(As, B2, c);
    #pragma unroll
    for (int i = 0; i < 2; i++) {
        #pragma unroll
        for (int h = 0; h < 2; h++) {
            int r = wr * 32 + i * 16 + qr + 8 * h;
            if (r < nvalid) {
                float* go = out_upd + (size_t)(row0 + r) * DIMS + wc * 64 + qc * 2;
                #pragma unroll
                for (int j = 0; j < 8; j++)
                    *(float2*)(go + j * 8) =
                        make_float2(c[i][j][2 * h], c[i][j][2 * h + 1]);
            }
        }
    }
}

// ---------------------------------------------------------------------------
// Launch: inputs x, edge_index, edge_attr, W_src, W_edge, W_rx, W_agg
// Output: concat(src_embed[N,D], edge_embed[E,D], rx_embed[N,D], updated[E,D])
// ---------------------------------------------------------------------------
extern "C" void kernel_launch(void* const* d_in, const int* in_sizes, int n_in,
                              void* d_out, int out_size) {
    const float* x     = (const float*)d_in[0];
    const void*  eidx  = d_in[1];
    const float* eattr = (const float*)d_in[2];
    const float* Wsrc  = (const float*)d_in[3];
    const float* Wedge = (const float*)d_in[4];
    const float* Wrx   = (const float*)d_in[5];
    const float* Wagg  = (const float*)d_in[6];

    int N = in_sizes[0] / DIMS;
    int E = in_sizes[2] / DIMS;

    float* out      = (float*)d_out;
    float* out_src  = out;
    float* out_edge = out_src + (size_t)N * DIMS;
    float* out_rx   = out_edge + (size_t)E * DIMS;
    float* out_upd  = out_rx + (size_t)N * DIMS;

    size_t smem_bytes = (size_t)(TILE_M + 2 * DIMS) * SROW * sizeof(float); // ~198 KB
    cudaFuncSetAttribute(node_kernel, cudaFuncAttributeMaxDynamicSharedMemorySize,
                         (int)smem_bytes);
    cudaFuncSetAttribute(edge_kernel, cudaFuncAttributeMaxDynamicSharedMemorySize,
                         (int)smem_bytes);

    detect_idx_kernel<<<1, 1>>>(eidx, (long long)N);
    node_kernel<<<(N + TILE_M - 1) / TILE_M, 256, smem_bytes>>>(
        x, Wsrc, Wrx, out_src, out_rx, N);
    edge_kernel<<<(E + TILE_M - 1) / TILE_M, 256, smem_bytes>>>(
        eattr, eidx, Wedge, Wagg, out_src, out_rx, out_edge, out_upd, E);
}

// round 5
// speedup vs baseline: 2.2716x; 1.0249x over previous
#include <cuda_runtime.h>
#include <cstdint>

#define DIMS 128
#define TILE 64
#define SROW 132          // smem row stride (floats): conflict-free frag access
#define NTHREADS 256

// smem layout in floats
#define SA0 0
#define SA1 (TILE * SROW)
#define SW1 (2 * TILE * SROW)
#define SW2 (SW1 + DIMS * SROW)
#define SMEM_FLOATS (SW2 + DIMS * SROW)   // 384*132 = 50688 floats = 202752 B

__device__ int g_idx_is64;

// ---------------------------------------------------------------------------
// helpers
// ---------------------------------------------------------------------------
__device__ __forceinline__ uint32_t smem_u32(const void* p) {
    uint32_t a;
    asm("{ .reg .u64 t; cvta.to.shared.u64 t, %1; cvt.u32.u64 %0, t; }"
        : "=r"(a) : "l"(p));
    return a;
}

__device__ __forceinline__ float f2tf_rna(float f) {
    uint32_t o;
    asm("cvt.rna.tf32.f32 %0, %1;" : "=r"(o) : "f"(f));
    return __uint_as_float(o);
}

__device__ __forceinline__ void cp16(uint32_t dst, const float* src) {
    asm volatile("cp.async.cg.shared.global [%0], [%1], 16;"
                 :: "r"(dst), "l"(src));
}
#define CP_COMMIT() asm volatile("cp.async.commit_group;" ::: "memory")
#define CP_WAIT1()  asm volatile("cp.async.wait_group 1;" ::: "memory")

__device__ __forceinline__ void mma8(float c[4], const uint32_t a[4],
                                     const uint32_t b[2]) {
    asm volatile(
        "mma.sync.aligned.m16n8k8.row.col.f32.tf32.tf32.f32 "
        "{%0,%1,%2,%3}, {%4,%5,%6,%7}, {%8,%9}, {%0,%1,%2,%3};"
        : "+f"(c[0]), "+f"(c[1]), "+f"(c[2]), "+f"(c[3])
        : "r"(a[0]), "r"(a[1]), "r"(a[2]), "r"(a[3]), "r"(b[0]), "r"(b[1]));
}

// Weight [128,128] fp32 -> smem (RNA-rounded to tf32), once per CTA.
__device__ __forceinline__ void load_w(const float* __restrict__ w, float* s) {
    int tid = threadIdx.x;
    #pragma unroll 4
    for (int idx = tid; idx < DIMS * 32; idx += NTHREADS) {
        int row = idx >> 5;
        int kc  = idx & 31;
        float4 v = *(const float4*)(w + row * DIMS + kc * 4);
        v.x = f2tf_rna(v.x); v.y = f2tf_rna(v.y);
        v.z = f2tf_rna(v.z); v.w = f2tf_rna(v.w);
        *(float4*)(s + row * SROW + kc * 4) = v;
    }
}

// Async prefetch of a 64-row tile (raw fp32; rounded later in registers).
__device__ __forceinline__ void prefetch_tile(const float* __restrict__ g,
                                              size_t row0, int nrows,
                                              uint32_t sbuf_bytes) {
    int tid = threadIdx.x;
    #pragma unroll
    for (int it = 0; it < (TILE * 32) / NTHREADS; it++) {
        int idx = tid + it * NTHREADS;
        int row = idx >> 5;
        int kc  = idx & 31;
        if (row < nrows)
            cp16(sbuf_bytes + (uint32_t)(row * SROW + kc * 4) * 4,
                 g + (row0 + row) * DIMS + kc * 4);
    }
}

// ---------------------------------------------------------------------------
// 64x128x128 warp-tiled tf32 GEMM: 8 warps as 2(row) x 4(col), warp tile 32x32.
// Accum c[i][j][4]: row = wr*32 + i*16 + qr + 8h, col = wc*32 + j*8 + qc*2(+1).
// CVT: apply RNA tf32 rounding to A fragments (raw-fp32 tiles from cp.async).
// ---------------------------------------------------------------------------
template <bool CVT>
__device__ __forceinline__ void gemm64(const float* __restrict__ As,
                                       const float* __restrict__ Bs,
                                       float c[2][4][4]) {
    int wid = threadIdx.x >> 5, lane = threadIdx.x & 31;
    int wr = wid & 1, wc = wid >> 1;
    int qr = lane >> 2, qc = lane & 3;
    const float* Ab = As + (wr * 32 + qr) * SROW + qc;
    const float* Bb = Bs + (wc * 32 + qr) * SROW + qc;

    #pragma unroll 4
    for (int k = 0; k < DIMS; k += 8) {
        uint32_t a[2][4], b[4][2];
        #pragma unroll
        for (int i = 0; i < 2; i++) {
            const float* p = Ab + i * 16 * SROW + k;
            float a0 = p[0], a1 = p[8 * SROW], a2 = p[4], a3 = p[8 * SROW + 4];
            if (CVT) {
                a0 = f2tf_rna(a0); a1 = f2tf_rna(a1);
                a2 = f2tf_rna(a2); a3 = f2tf_rna(a3);
            }
            a[i][0] = __float_as_uint(a0); a[i][1] = __float_as_uint(a1);
            a[i][2] = __float_as_uint(a2); a[i][3] = __float_as_uint(a3);
        }
        #pragma unroll
        for (int j = 0; j < 4; j++) {
            const float* p = Bb + j * 8 * SROW + k;
            b[j][0] = __float_as_uint(p[0]);
            b[j][1] = __float_as_uint(p[4]);
        }
        #pragma unroll
        for (int i = 0; i < 2; i++)
            #pragma unroll
            for (int j = 0; j < 4; j++) mma8(c[i][j], a[i], b[j]);
    }
}

__device__ __forceinline__ void acc_zero(float c[2][4][4]) {
    #pragma unroll
    for (int i = 0; i < 2; i++)
        #pragma unroll
        for (int j = 0; j < 4; j++)
            #pragma unroll
            for (int q = 0; q < 4; q++) c[i][j][q] = 0.f;
}

// ---------------------------------------------------------------------------
// Node kernel: persistent over tiles; src = x@Wsrc^T, rx = x@Wrx^T.
// Also performs edge_index dtype detection (block 0).
// ---------------------------------------------------------------------------
extern __shared__ float smem[];

__global__ void __launch_bounds__(NTHREADS, 1)
node_kernel(const float* __restrict__ x, const float* __restrict__ Wsrc,
            const float* __restrict__ Wrx, const void* __restrict__ eidx,
            float* __restrict__ out_src, float* __restrict__ out_rx,
            int n_nodes, int tiles_per_cta, int ntiles) {
    if (blockIdx.x == 0 && threadIdx.x == 0) {
        const long long* p = (const long long*)eidx;
        int ok = 1;
        for (int i = 0; i < 32; i++) {
            long long v = p[i];
            if (v < 0 || v >= (long long)n_nodes) ok = 0;
        }
        g_idx_is64 = ok;
    }

    uint32_t sb = smem_u32(smem);
    int t0 = blockIdx.x * tiles_per_cta;
    if (t0 >= ntiles) return;
    int t1 = min(t0 + tiles_per_cta, ntiles);

    load_w(Wsrc, smem + SW1);
    load_w(Wrx,  smem + SW2);
    prefetch_tile(x, (size_t)t0 * TILE, min(TILE, n_nodes - t0 * TILE), sb + SA0 * 4);
    CP_COMMIT();

    int wid = threadIdx.x >> 5, lane = threadIdx.x & 31;
    int wr = wid & 1, wc = wid >> 1;
    int qr = lane >> 2, qc = lane & 3;

    for (int t = t0; t < t1; t++) {
        int buf = (t - t0) & 1;
        float* A = smem + (buf ? SA1 : SA0);
        if (t + 1 < t1)
            prefetch_tile(x, (size_t)(t + 1) * TILE,
                          min(TILE, n_nodes - (t + 1) * TILE),
                          sb + (buf ? SA0 : SA1) * 4);
        CP_COMMIT();
        CP_WAIT1();
        __syncthreads();

        int nvalid = min(TILE, n_nodes - t * TILE);
        float c[2][4][4];

        #pragma unroll
        for (int g = 0; g < 2; g++) {
            float* outp = g ? out_rx : out_src;
            acc_zero(c);
            if (g == 0) gemm64<true>(A, smem + SW1, c);
            else        gemm64<true>(A, smem + SW2, c);
            #pragma unroll
            for (int i = 0; i < 2; i++)
                #pragma unroll
                for (int h = 0; h < 2; h++) {
                    int r = wr * 32 + i * 16 + qr + 8 * h;
                    if (r < nvalid) {
                        float* gp = outp + ((size_t)t * TILE + r) * DIMS
                                  + wc * 32 + qc * 2;
                        #pragma unroll
                        for (int j = 0; j < 4; j++)
                            *(float2*)(gp + j * 8) =
                                make_float2(c[i][j][2 * h], c[i][j][2 * h + 1]);
                    }
                }
        }
        __syncthreads();   // protect A before next iteration's prefetch reuses it
    }
}

// ---------------------------------------------------------------------------
// Edge kernel: persistent over tiles.
//   edge_embed = edge_attr @ Wedge^T  (written out)
//   agg = edge_embed + src[u] + rx[v] (RNA, rebuilt in A buffer)
//   updated = agg @ Wagg^T            (written out)
// ---------------------------------------------------------------------------
__global__ void __launch_bounds__(NTHREADS, 1)
edge_kernel(const float* __restrict__ eattr, const void* __restrict__ eidx,
            const float* __restrict__ Wedge, const float* __restrict__ Wagg,
            const float* __restrict__ src_embed, const float* __restrict__ rx_embed,
            float* __restrict__ out_edge, float* __restrict__ out_upd,
            int n_edges, int tiles_per_cta, int ntiles) {
    uint32_t sb = smem_u32(smem);
    int t0 = blockIdx.x * tiles_per_cta;
    if (t0 >= ntiles) return;
    int t1 = min(t0 + tiles_per_cta, ntiles);

    load_w(Wedge, smem + SW1);
    load_w(Wagg,  smem + SW2);
    prefetch_tile(eattr, (size_t)t0 * TILE, min(TILE, n_edges - t0 * TILE),
                  sb + SA0 * 4);
    CP_COMMIT();

    int wid = threadIdx.x >> 5, lane = threadIdx.x & 31;
    int wr = wid & 1, wc = wid >> 1;
    int qr = lane >> 2, qc = lane & 3;
    int is64 = g_idx_is64;
    const long long* p64 = (const long long*)eidx;
    const int*       p32 = (const int*)eidx;

    for (int t = t0; t < t1; t++) {
        int buf = (t - t0) & 1;
        float* A = smem + (buf ? SA1 : SA0);
        if (t + 1 < t1)
            prefetch_tile(eattr, (size_t)(t + 1) * TILE,
                          min(TILE, n_edges - (t + 1) * TILE),
                          sb + (buf ? SA0 : SA1) * 4);
        CP_COMMIT();
        CP_WAIT1();
        __syncthreads();

        int nvalid = min(TILE, n_edges - t * TILE);
        float c[2][4][4];
        acc_zero(c);
        gemm64<true>(A, smem + SW1, c);       // edge_embed in regs
        __syncthreads();                       // all reads of A done

        // Epilogue 1: write edge_embed, gather src[u]+rx[v], agg (RNA) -> A.
        #pragma unroll
        for (int i = 0; i < 2; i++)
            #pragma unroll
            for (int h = 0; h < 2; h++) {
                int r = wr * 32 + i * 16 + qr + 8 * h;
                if (r < nvalid) {
                    size_t e = (size_t)t * TILE + r;
                    long long u, v;
                    if (is64) { u = p64[e]; v = p64[(size_t)n_edges + e]; }
                    else      { u = p32[e]; v = p32[(size_t)n_edges + e]; }
                    int colb = wc * 32 + qc * 2;
                    float* ge = out_edge + e * DIMS + colb;
                    const float* su = src_embed + (size_t)u * DIMS + colb;
                    const float* rv = rx_embed  + (size_t)v * DIMS + colb;
                    float* sa = A + r * SROW + colb;
                    #pragma unroll
                    for (int j = 0; j < 4; j++) {
                        float2 a = make_float2(c[i][j][2 * h], c[i][j][2 * h + 1]);
                        *(float2*)(ge + j * 8) = a;
                        float2 s2 = *(const float2*)(su + j * 8);
                        float2 r2 = *(const float2*)(rv + j * 8);
                        a.x = f2tf_rna(a.x + s2.x + r2.x);
                        a.y = f2tf_rna(a.y + s2.y + r2.y);
                        *(float2*)(sa + j * 8) = a;
                    }
                }
            }
        __syncthreads();

        acc_zero(c);
        gemm64<false>(A, smem + SW2, c);      // updated_edge
        #pragma unroll
        for (int i = 0; i < 2; i++)
            #pragma unroll
            for (int h = 0; h < 2; h++) {
                int r = wr * 32 + i * 16 + qr + 8 * h;
                if (r < nvalid) {
                    float* go = out_upd + ((size_t)t * TILE + r) * DIMS
                              + wc * 32 + qc * 2;
                    #pragma unroll
                    for (int j = 0; j < 4; j++)
                        *(float2*)(go + j * 8) =
                            make_float2(c[i][j][2 * h], c[i][j][2 * h + 1]);
                }
            }
        __syncthreads();   // protect A before next iteration's prefetch reuses it
    }
}

// ---------------------------------------------------------------------------
// Launch: inputs x, edge_index, edge_attr, W_src, W_edge, W_rx, W_agg
// Output: concat(src_embed[N,D], edge_embed[E,D], rx_embed[N,D], updated[E,D])
// ---------------------------------------------------------------------------
extern "C" void kernel_launch(void* const* d_in, const int* in_sizes, int n_in,
                              void* d_out, int out_size) {
    const float* x     = (const float*)d_in[0];
    const void*  eidx  = d_in[1];
    const float* eattr = (const float*)d_in[2];
    const float* Wsrc  = (const float*)d_in[3];
    const float* Wedge = (const float*)d_in[4];
    const float* Wrx   = (const float*)d_in[5];
    const float* Wagg  = (const float*)d_in[6];

    int N = in_sizes[0] / DIMS;
    int E = in_sizes[2] / DIMS;

    float* out      = (float*)d_out;
    float* out_src  = out;
    float* out_edge = out_src + (size_t)N * DIMS;
    float* out_rx   = out_edge + (size_t)E * DIMS;
    float* out_upd  = out_rx + (size_t)N * DIMS;

    int ntiles_n = (N + TILE - 1) / TILE;
    int ntiles_e = (E + TILE - 1) / TILE;
    int tpc_n = (ntiles_n + 147) / 148;          // ~1 wave of CTAs
    int grid_n = (ntiles_n + tpc_n - 1) / tpc_n;
    int tpc_e = (ntiles_e + 4 * 148 - 1) / (4 * 148);  // ~4 waves
    int grid_e = (ntiles_e + tpc_e - 1) / tpc_e;

    size_t smem_bytes = (size_t)SMEM_FLOATS * sizeof(float);  // 202752 B
    cudaFuncSetAttribute(node_kernel, cudaFuncAttributeMaxDynamicSharedMemorySize,
                         (int)smem_bytes);
    cudaFuncSetAttribute(edge_kernel, cudaFuncAttributeMaxDynamicSharedMemorySize,
                         (int)smem_bytes);

    node_kernel<<<grid_n, NTHREADS, smem_bytes>>>(
        x, Wsrc, Wrx, eidx, out_src, out_rx, N, tpc_n, ntiles_n);
    edge_kernel<<<grid_e, NTHREADS, smem_bytes>>>(
        eattr, eidx, Wedge, Wagg, out_src, out_rx, out_edge, out_upd,
        E, tpc_e, ntiles_e);
}